// round 7
// baseline (speedup 1.0000x reference)
#include <cuda_runtime.h>
#include <cuda_bf16.h>
#include <math.h>
#include <stdint.h>

#define T_DIM 8192
#define D_DIM 128
#define BM 128
#define BN 64
#define NSPLIT 2
#define KEYS_PER_SPLIT (T_DIM / NSPLIT)   /* 4096 */
#define NTILES (KEYS_PER_SPLIT / BN)      /* 64   */
#define NTH 256
#define LOG2E 1.4426950408889634f

/* smem: THREE K buffers (KH 16K + KL 16K each) + qbias triple buffer */
#define BUF_STRIDE 32768
#define OFF_KL_REL 16384
#define OFF_QB (3 * BUF_STRIDE)           /* 98304 */
#define SMEM_SZ (OFF_QB + 3 * 256 + 128)  /* 99200 */

#define HPART_BLKS 512

__device__ float  g_qbias[T_DIM];
__device__ float  g_O[NSPLIT * T_DIM * D_DIM];
__device__ float4 g_ml[NSPLIT * T_DIM];   /* (m_scale, p_max, l, 0) base-2 domain */
__device__ float  g_b[T_DIM];
__device__ float  g_hpart[HPART_BLKS * D_DIM];
__device__ float  g_h[D_DIM];

__device__ __forceinline__ uint32_t smem_u32(const void* p) {
    uint32_t a;
    asm("{ .reg .u64 t; cvta.to.shared.u64 t, %1; cvt.u32.u64 %0, t; }" : "=r"(a) : "l"(p));
    return a;
}
__device__ __forceinline__ float ex2(float x) {
    float y;
    asm("ex2.approx.f32 %0, %1;" : "=f"(y) : "f"(x));
    return y;
}
/* pack two floats to bf16x2: lower 16 = lo, upper 16 = hi */
__device__ __forceinline__ uint32_t pack_bf16x2(float lo, float hi) {
    uint32_t r;
    asm("cvt.rn.bf16x2.f32 %0, %1, %2;" : "=r"(r) : "f"(hi), "f"(lo));
    return r;
}
/* split a pair of floats into packed bf16 hi + packed bf16 residual lo */
__device__ __forceinline__ void split2(float a, float b, uint32_t& hi, uint32_t& lo) {
    hi = pack_bf16x2(a, b);
    float fa = __uint_as_float(hi << 16);
    float fb = __uint_as_float(hi & 0xffff0000u);
    lo = pack_bf16x2(a - fa, b - fb);
}

#define LDSM4(r, addr) \
    asm volatile("ldmatrix.sync.aligned.m8n8.x4.shared.b16 {%0,%1,%2,%3}, [%4];" \
        : "=r"((r)[0]), "=r"((r)[1]), "=r"((r)[2]), "=r"((r)[3]) : "r"(addr))
#define LDSM4T(r, addr) \
    asm volatile("ldmatrix.sync.aligned.m8n8.x4.trans.shared.b16 {%0,%1,%2,%3}, [%4];" \
        : "=r"((r)[0]), "=r"((r)[1]), "=r"((r)[2]), "=r"((r)[3]) : "r"(addr))
#define MMA(c, a, b) \
    asm volatile("mma.sync.aligned.m16n8k16.row.col.f32.bf16.bf16.f32 " \
        "{%0,%1,%2,%3}, {%4,%5,%6,%7}, {%8,%9}, {%0,%1,%2,%3};" \
        : "+f"((c)[0]), "+f"((c)[1]), "+f"((c)[2]), "+f"((c)[3]) \
        : "r"((a)[0]), "r"((a)[1]), "r"((a)[2]), "r"((a)[3]), "r"((b)[0]), "r"((b)[1]))

/* ---------------- flash building blocks ---------------- */
__device__ __forceinline__ void gemm1_tile(
    float (&S)[8][4], uint32_t base,
    const uint32_t (&aQh)[8][4], const uint32_t (&aQl)[8][4],
    int b1_key, int b1_cs)
{
    #pragma unroll
    for (int nt = 0; nt < 8; ++nt) {
        S[nt][0] = 0.f; S[nt][1] = 0.f; S[nt][2] = 0.f; S[nt][3] = 0.f;
    }
    #pragma unroll
    for (int kt = 0; kt < 8; ++kt) {
        uint32_t bh[4][4];
        #pragma unroll
        for (int np = 0; np < 4; ++np) {
            int key = np * 16 + b1_key;
            int ch  = kt * 2 + b1_cs;
            LDSM4(bh[np], base + key * 256 + ((ch ^ (key & 7)) << 4));
        }
        #pragma unroll
        for (int np = 0; np < 4; ++np) {
            MMA(S[2 * np],     aQh[kt], &bh[np][0]);
            MMA(S[2 * np + 1], aQh[kt], &bh[np][2]);
        }
        #pragma unroll
        for (int np = 0; np < 4; ++np) {
            MMA(S[2 * np],     aQl[kt], &bh[np][0]);
            MMA(S[2 * np + 1], aQl[kt], &bh[np][2]);
        }
        #pragma unroll
        for (int np = 0; np < 4; ++np) {   /* reuse regs for Kl */
            int key = np * 16 + b1_key;
            int ch  = kt * 2 + b1_cs;
            LDSM4(bh[np], base + OFF_KL_REL + key * 256 + ((ch ^ (key & 7)) << 4));
        }
        #pragma unroll
        for (int np = 0; np < 4; ++np) {
            MMA(S[2 * np],     aQh[kt], &bh[np][0]);
            MMA(S[2 * np + 1], aQh[kt], &bh[np][2]);
        }
    }
}

__device__ __forceinline__ void softmax_tile(
    float (&S)[8][4], uint32_t (&P)[8][2],
    const float* qbp, int lane, bool first,
    float& msc0, float& msc1, float& l0r, float& l1r, float& pm0, float& pm1)
{
    #pragma unroll
    for (int nt = 0; nt < 8; ++nt) {
        float2 tq = *(const float2*)&qbp[nt * 8 + (lane & 3) * 2];
        S[nt][0] += tq.x; S[nt][1] += tq.y;
        S[nt][2] += tq.x; S[nt][3] += tq.y;
    }
    if (first) {   /* one-time static scale = row max of first processed tile */
        float mx0 = -INFINITY, mx1 = -INFINITY;
        #pragma unroll
        for (int nt = 0; nt < 8; ++nt) {
            mx0 = fmaxf(mx0, fmaxf(S[nt][0], S[nt][1]));
            mx1 = fmaxf(mx1, fmaxf(S[nt][2], S[nt][3]));
        }
        mx0 = fmaxf(mx0, __shfl_xor_sync(0xffffffffu, mx0, 1));
        mx0 = fmaxf(mx0, __shfl_xor_sync(0xffffffffu, mx0, 2));
        mx1 = fmaxf(mx1, __shfl_xor_sync(0xffffffffu, mx1, 1));
        mx1 = fmaxf(mx1, __shfl_xor_sync(0xffffffffu, mx1, 2));
        msc0 = mx0; msc1 = mx1;
    }
    #pragma unroll
    for (int nt = 0; nt < 8; ++nt) {
        float p0 = ex2(S[nt][0] - msc0);
        float p1 = ex2(S[nt][1] - msc0);
        float p2 = ex2(S[nt][2] - msc1);
        float p3 = ex2(S[nt][3] - msc1);
        l0r += p0 + p1;  l1r += p2 + p3;
        pm0 = fmaxf(pm0, fmaxf(p0, p1));
        pm1 = fmaxf(pm1, fmaxf(p2, p3));
        P[nt][0] = pack_bf16x2(p0, p1);
        P[nt][1] = pack_bf16x2(p2, p3);
    }
}

__device__ __forceinline__ void gemm2_tile(
    float (&O)[16][4], const uint32_t (&P)[8][2],
    uint32_t base, int b2_key, int b2_cs)
{
    #pragma unroll
    for (int kt2 = 0; kt2 < 4; ++kt2) {
        uint32_t aP[4] = { P[2 * kt2][0], P[2 * kt2][1],
                           P[2 * kt2 + 1][0], P[2 * kt2 + 1][1] };
        const int key = kt2 * 16 + b2_key;
        const uint32_t krow = base + key * 256;   /* KH region */
        #pragma unroll
        for (int dp = 0; dp < 8; ++dp) {
            uint32_t bv[4];
            int ch = dp * 2 + b2_cs;
            LDSM4T(bv, krow + ((ch ^ (key & 7)) << 4));
            MMA(O[2 * dp],     aP, &bv[0]);
            MMA(O[2 * dp + 1], aP, &bv[2]);
        }
    }
}

/* ================= K0: qbias[j] = (question[j] . w_q) * log2(e) ================= */
__global__ void qbias_kernel(const float* __restrict__ x, const float* __restrict__ kern) {
    int j = blockIdx.x * 8 + (threadIdx.x >> 5);
    int lane = threadIdx.x & 31;
    const float* q  = x + (size_t)T_DIM * D_DIM + (size_t)j * D_DIM;
    const float* wq = kern + D_DIM;
    float s = q[lane] * wq[lane] + q[lane + 32] * wq[lane + 32]
            + q[lane + 64] * wq[lane + 64] + q[lane + 96] * wq[lane + 96];
    #pragma unroll
    for (int off = 16; off; off >>= 1) s += __shfl_xor_sync(0xffffffffu, s, off);
    if (lane == 0) g_qbias[j] = s * LOG2E;
}

/* ================= K1: ping-pong HMMA flash ================= */
__global__ void __launch_bounds__(NTH, 1)
flash_kernel(const float* __restrict__ x, const float* __restrict__ kern)
{
    extern __shared__ char smem[];
    const uint32_t sb = smem_u32(smem);

    const int tid  = threadIdx.x;
    const int lane = tid & 31;
    const int w    = tid >> 5;
    const int g    = w >> 2;              /* ping-pong group */
    const int rowblk = blockIdx.x >> 1;
    const int split  = blockIdx.x & 1;
    const int row0 = rowblk * BM;

    const float* ctx = x;
    const float* qst = x + (size_t)T_DIM * D_DIM;
    const float* wm  = kern + 2 * D_DIM;

    /* ---- prologue A: Q' = ctx*w_m*log2e → bf16 hi/lo staged in bufs 0/1 ---- */
    #pragma unroll
    for (int i = 0; i < 8; ++i) {
        int idx = tid + i * NTH;
        int row = idx >> 4, ch = idx & 15;
        const float* src = ctx + (size_t)(row0 + row) * D_DIM + ch * 8;
        float4 v0 = *(const float4*)src, v1 = *(const float4*)(src + 4);
        float4 w0 = *(const float4*)&wm[ch * 8], w1 = *(const float4*)&wm[ch * 8 + 4];
        w0.x *= LOG2E; w0.y *= LOG2E; w0.z *= LOG2E; w0.w *= LOG2E;
        w1.x *= LOG2E; w1.y *= LOG2E; w1.z *= LOG2E; w1.w *= LOG2E;
        v0.x *= w0.x; v0.y *= w0.y; v0.z *= w0.z; v0.w *= w0.w;
        v1.x *= w1.x; v1.y *= w1.y; v1.z *= w1.z; v1.w *= w1.w;
        uint32_t h0, l0, h1, l1, h2, l2, h3, l3;
        split2(v0.x, v0.y, h0, l0); split2(v0.z, v0.w, h1, l1);
        split2(v1.x, v1.y, h2, l2); split2(v1.z, v1.w, h3, l3);
        uint32_t off = row * 256 + ((ch ^ (row & 7)) << 4);
        *(uint4*)(smem + off)              = make_uint4(h0, h1, h2, h3);
        *(uint4*)(smem + BUF_STRIDE + off) = make_uint4(l0, l1, l2, l3);
    }
    __syncthreads();

    /* ---- prologue B: loop-invariant Q A-fragments into registers ---- */
    const int m0 = w * 16;
    const int a_row = m0 + (lane & 15);
    const int a_cs  = (lane >> 4);
    uint32_t aQh[8][4], aQl[8][4];
    #pragma unroll
    for (int kt = 0; kt < 8; ++kt) {
        int ach = kt * 2 + a_cs;
        uint32_t aoff = a_row * 256 + ((ach ^ (a_row & 7)) << 4);
        LDSM4(aQh[kt], sb + aoff);
        LDSM4(aQl[kt], sb + BUF_STRIDE + aoff);
    }
    __syncthreads();   /* Q staging reads done — buffers now free for K */

    /* ---- prologue C: K tile 0 → buf0 ---- */
    const int srow = tid >> 4, sch = tid & 15;
    {
        const int kbase = split * KEYS_PER_SPLIT;
        #pragma unroll
        for (int i = 0; i < 4; ++i) {
            int row = srow + 16 * i;
            const float* src = qst + (size_t)(kbase + row) * D_DIM + sch * 8;
            float4 v0 = *(const float4*)src, v1 = *(const float4*)(src + 4);
            uint32_t h0, l0, h1, l1, h2, l2, h3, l3;
            split2(v0.x, v0.y, h0, l0); split2(v0.z, v0.w, h1, l1);
            split2(v1.x, v1.y, h2, l2); split2(v1.z, v1.w, h3, l3);
            uint32_t off = row * 256 + ((sch ^ (row & 7)) << 4);
            *(uint4*)(smem + off)              = make_uint4(h0, h1, h2, h3);
            *(uint4*)(smem + OFF_KL_REL + off) = make_uint4(l0, l1, l2, l3);
        }
        if (tid < BN) ((float*)(smem + OFF_QB))[tid] = g_qbias[kbase + tid];
    }

    float O[16][4];
    float msc0 = 0.f, msc1 = 0.f;
    float l0r = 0.f, l1r = 0.f;
    float pm0 = 0.f, pm1 = 0.f;
    #pragma unroll
    for (int nt = 0; nt < 16; ++nt)
        #pragma unroll
        for (int c = 0; c < 4; ++c) O[nt][c] = 0.f;

    const int b1_key = ((lane >> 4) << 3) + (lane & 7);
    const int b1_cs  = ((lane >> 3) & 1);
    const int b2_key = ((lane >> 3) & 1) * 8 + (lane & 7);
    const int b2_cs  = (lane >> 4);

    float S[8][4];        /* survives across the barrier for group 1 */
    uint32_t P[8][2];

    for (int t = 0; t < NTILES; ++t) {
        __syncthreads();   /* buf[t%3] ready; buf[(t+1)%3] free for writing */
        const uint32_t bufR = (uint32_t)(t % 3) * BUF_STRIDE;
        const uint32_t bufW = (uint32_t)((t + 1) % 3) * BUF_STRIDE;
        const bool has_next = (t + 1 < NTILES);

        /* stage fp32 loads of K tile t+1 (latency hidden under compute) */
        float4 sA[4], sB[4];
        float sqb = 0.f;
        if (has_next) {
            const int kb = split * KEYS_PER_SPLIT + (t + 1) * BN;
            #pragma unroll
            for (int i = 0; i < 4; ++i) {
                const float* src = qst + (size_t)(kb + srow + 16 * i) * D_DIM + sch * 8;
                sA[i] = *(const float4*)src;
                sB[i] = *(const float4*)(src + 4);
            }
            if (tid < BN) sqb = g_qbias[kb + tid];
        }

        if (g == 0) {
            /* G0: GEMM1(t) → store(t+1) → softmax(t) → GEMM2(t) */
            gemm1_tile(S, sb + bufR, aQh, aQl, b1_key, b1_cs);
            if (has_next) {
                #pragma unroll
                for (int i = 0; i < 4; ++i) {
                    int row = srow + 16 * i;
                    uint32_t h0, l0, h1, l1, h2, l2, h3, l3;
                    split2(sA[i].x, sA[i].y, h0, l0); split2(sA[i].z, sA[i].w, h1, l1);
                    split2(sB[i].x, sB[i].y, h2, l2); split2(sB[i].z, sB[i].w, h3, l3);
                    uint32_t off = row * 256 + ((sch ^ (row & 7)) << 4);
                    *(uint4*)(smem + bufW + off)              = make_uint4(h0, h1, h2, h3);
                    *(uint4*)(smem + bufW + OFF_KL_REL + off) = make_uint4(l0, l1, l2, l3);
                }
                if (tid < BN) ((float*)(smem + OFF_QB + ((t + 1) % 3) * 256))[tid] = sqb;
            }
            softmax_tile(S, P, (const float*)(smem + OFF_QB + (t % 3) * 256),
                         lane, t == 0, msc0, msc1, l0r, l1r, pm0, pm1);
            gemm2_tile(O, P, sb + bufR, b2_key, b2_cs);
        } else {
            /* G1: softmax(t-1) → GEMM2(t-1) → store(t+1) → GEMM1(t) */
            if (t > 0) {
                const uint32_t bufP = (uint32_t)((t - 1) % 3) * BUF_STRIDE;
                softmax_tile(S, P, (const float*)(smem + OFF_QB + ((t - 1) % 3) * 256),
                             lane, t == 1, msc0, msc1, l0r, l1r, pm0, pm1);
                gemm2_tile(O, P, sb + bufP, b2_key, b2_cs);
            }
            if (has_next) {
                #pragma unroll
                for (int i = 0; i < 4; ++i) {
                    int row = srow + 16 * i;
                    uint32_t h0, l0, h1, l1, h2, l2, h3, l3;
                    split2(sA[i].x, sA[i].y, h0, l0); split2(sA[i].z, sA[i].w, h1, l1);
                    split2(sB[i].x, sB[i].y, h2, l2); split2(sB[i].z, sB[i].w, h3, l3);
                    uint32_t off = row * 256 + ((sch ^ (row & 7)) << 4);
                    *(uint4*)(smem + bufW + off)              = make_uint4(h0, h1, h2, h3);
                    *(uint4*)(smem + bufW + OFF_KL_REL + off) = make_uint4(l0, l1, l2, l3);
                }
                if (tid < BN) ((float*)(smem + OFF_QB + ((t + 1) % 3) * 256))[tid] = sqb;
            }
            gemm1_tile(S, sb + bufR, aQh, aQl, b1_key, b1_cs);
        }
    }

    /* G1 finishes its lagging tile */
    if (g == 1) {
        const uint32_t bufP = (uint32_t)((NTILES - 1) % 3) * BUF_STRIDE;
        softmax_tile(S, P, (const float*)(smem + OFF_QB + ((NTILES - 1) % 3) * 256),
                     lane, false, msc0, msc1, l0r, l1r, pm0, pm1);
        gemm2_tile(O, P, sb + bufP, b2_key, b2_cs);
    }

    /* ---- epilogue: one-time l / pm reductions, write O and (msc,pm,l) ---- */
    {
        l0r += __shfl_xor_sync(0xffffffffu, l0r, 1);
        l0r += __shfl_xor_sync(0xffffffffu, l0r, 2);
        l1r += __shfl_xor_sync(0xffffffffu, l1r, 1);
        l1r += __shfl_xor_sync(0xffffffffu, l1r, 2);
        pm0 = fmaxf(pm0, __shfl_xor_sync(0xffffffffu, pm0, 1));
        pm0 = fmaxf(pm0, __shfl_xor_sync(0xffffffffu, pm0, 2));
        pm1 = fmaxf(pm1, __shfl_xor_sync(0xffffffffu, pm1, 1));
        pm1 = fmaxf(pm1, __shfl_xor_sync(0xffffffffu, pm1, 2));

        int r1 = row0 + m0 + (lane >> 2);
        int r2 = r1 + 8;
        if ((lane & 3) == 0) {
            g_ml[(size_t)split * T_DIM + r1] = make_float4(msc0, pm0, l0r, 0.f);
            g_ml[(size_t)split * T_DIM + r2] = make_float4(msc1, pm1, l1r, 0.f);
        }
        float* o1 = g_O + ((size_t)split * T_DIM + r1) * D_DIM + (lane & 3) * 2;
        float* o2 = g_O + ((size_t)split * T_DIM + r2) * D_DIM + (lane & 3) * 2;
        #pragma unroll
        for (int nt = 0; nt < 16; ++nt) {
            *(float2*)(o1 + nt * 8) = make_float2(O[nt][0], O[nt][1]);
            *(float2*)(o2 + nt * 8) = make_float2(O[nt][2], O[nt][3]);
        }
    }
}

/* ============ K2: combine splits, write out cols [0,384), emit b ============ */
__global__ void combine_kernel(const float* __restrict__ x, float* __restrict__ out) {
    int row  = (blockIdx.x * blockDim.x + threadIdx.x) >> 5;
    int lane = threadIdx.x & 31;
    float4 ml[NSPLIT];
    float M = -INFINITY;
    #pragma unroll
    for (int s = 0; s < NSPLIT; ++s) {
        ml[s] = g_ml[(size_t)s * T_DIM + row];
        M = fmaxf(M, ml[s].x);
    }
    float L = 0.f, e[NSPLIT], bmax = 0.f;
    #pragma unroll
    for (int s = 0; s < NSPLIT; ++s) {
        e[s] = ex2(ml[s].x - M);
        L += ml[s].z * e[s];
        bmax = fmaxf(bmax, ml[s].y * e[s]);
    }
    float invL = 1.0f / L;
    float4 U = make_float4(0.f, 0.f, 0.f, 0.f);
    #pragma unroll
    for (int s = 0; s < NSPLIT; ++s) {
        float4 o = *(const float4*)&g_O[((size_t)s * T_DIM + row) * D_DIM + lane * 4];
        U.x += o.x * e[s]; U.y += o.y * e[s]; U.z += o.z * e[s]; U.w += o.w * e[s];
    }
    U.x *= invL; U.y *= invL; U.z *= invL; U.w *= invL;
    float4 c = *(const float4*)&x[(size_t)row * D_DIM + lane * 4];
    float* orow = out + (size_t)row * (4 * D_DIM);
    *(float4*)&orow[lane * 4]             = c;
    *(float4*)&orow[D_DIM + lane * 4]     = U;
    *(float4*)&orow[2 * D_DIM + lane * 4] = make_float4(c.x * U.x, c.y * U.y, c.z * U.z, c.w * U.w);
    if (lane == 0) g_b[row] = bmax * invL;   /* b = max_j A */
}

/* ============ K3/K4/K5: h = b @ context; out cols [384,512) = ctx*h ============ */
__global__ void hpart_kernel(const float* __restrict__ x) {
    int d = threadIdx.x;
    int r0 = blockIdx.x * (T_DIM / HPART_BLKS);
    float s = 0.f;
    #pragma unroll
    for (int r = 0; r < T_DIM / HPART_BLKS; ++r)
        s += g_b[r0 + r] * x[(size_t)(r0 + r) * D_DIM + d];
    g_hpart[blockIdx.x * D_DIM + d] = s;
}
__global__ void hreduce_kernel() {
    int d = threadIdx.x;
    float s = 0.f;
    #pragma unroll 16
    for (int b = 0; b < HPART_BLKS; ++b) s += g_hpart[b * D_DIM + d];
    g_h[d] = s;
}
__global__ void hwrite_kernel(const float* __restrict__ x, float* __restrict__ out) {
    int idx = blockIdx.x * blockDim.x + threadIdx.x;
    int row = idx >> 5;
    int dq  = idx & 31;
    float4 c = ((const float4*)x)[(size_t)row * 32 + dq];
    float4 h = ((const float4*)g_h)[dq];
    ((float4*)out)[(size_t)row * 128 + 96 + dq] =
        make_float4(c.x * h.x, c.y * h.y, c.z * h.z, c.w * h.w);
}

/* ============================================================================ */
extern "C" void kernel_launch(void* const* d_in, const int* in_sizes, int n_in,
                              void* d_out, int out_size) {
    const float* x    = (const float*)d_in[0];
    const float* kern = (const float*)d_in[1];
    float* out = (float*)d_out;

    cudaFuncSetAttribute(flash_kernel, cudaFuncAttributeMaxDynamicSharedMemorySize, SMEM_SZ);

    qbias_kernel<<<T_DIM / 8, 256>>>(x, kern);
    flash_kernel<<<(T_DIM / BM) * NSPLIT, NTH, SMEM_SZ>>>(x, kern);
    combine_kernel<<<(T_DIM * 32) / 256, 256>>>(x, out);
    hpart_kernel<<<HPART_BLKS, 128>>>(x);
    hreduce_kernel<<<1, 128>>>();
    hwrite_kernel<<<(T_DIM * D_DIM / 4) / 256, 256>>>(x, out);
}

// round 8
// speedup vs baseline: 1.0057x; 1.0057x over previous
#include <cuda_runtime.h>
#include <cuda_bf16.h>
#include <math.h>
#include <stdint.h>

#define T_DIM 8192
#define D_DIM 128
#define BM 128
#define BN 64
#define NSPLIT 2
#define KEYS_PER_SPLIT (T_DIM / NSPLIT)   /* 4096 */
#define NTILES (KEYS_PER_SPLIT / BN)      /* 64   */
#define NTILES_ALL (T_DIM / BN)           /* 128  */
#define NTH 256
#define LOG2E 1.4426950408889634f

/* smem: THREE 32KB K buffers (KH 16K | KL 16K) + qbias triple buffer */
#define BUF_STRIDE 32768
#define OFF_KL_REL 16384
#define OFF_QB (3 * BUF_STRIDE)           /* 98304 */
#define SMEM_SZ (OFF_QB + 3 * 256 + 128)

#define HPART_BLKS 512

__device__ float  g_qbias[T_DIM];
__device__ unsigned char g_kswz[NTILES_ALL * BUF_STRIDE];   /* pre-swizzled Kh|Kl per tile */
__device__ float  g_O[NSPLIT * T_DIM * D_DIM];
__device__ float4 g_ml[NSPLIT * T_DIM];   /* (m_scale, p_max, l, 0) base-2 domain */
__device__ float  g_b[T_DIM];
__device__ float  g_hpart[HPART_BLKS * D_DIM];
__device__ float  g_h[D_DIM];

__device__ __forceinline__ uint32_t smem_u32(const void* p) {
    uint32_t a;
    asm("{ .reg .u64 t; cvta.to.shared.u64 t, %1; cvt.u32.u64 %0, t; }" : "=r"(a) : "l"(p));
    return a;
}
__device__ __forceinline__ float ex2(float x) {
    float y;
    asm("ex2.approx.f32 %0, %1;" : "=f"(y) : "f"(x));
    return y;
}
/* pack two floats to bf16x2: lower 16 = first arg */
__device__ __forceinline__ uint32_t pack_bf16x2(float lo, float hi) {
    uint32_t r;
    asm("cvt.rn.bf16x2.f32 %0, %1, %2;" : "=r"(r) : "f"(hi), "f"(lo));
    return r;
}
__device__ __forceinline__ void split2(float a, float b, uint32_t& hi, uint32_t& lo) {
    hi = pack_bf16x2(a, b);
    float fa = __uint_as_float(hi << 16);
    float fb = __uint_as_float(hi & 0xffff0000u);
    lo = pack_bf16x2(a - fa, b - fb);
}

#define LDSM4(r, addr) \
    asm volatile("ldmatrix.sync.aligned.m8n8.x4.shared.b16 {%0,%1,%2,%3}, [%4];" \
        : "=r"((r)[0]), "=r"((r)[1]), "=r"((r)[2]), "=r"((r)[3]) : "r"(addr))
#define LDSM4T(r, addr) \
    asm volatile("ldmatrix.sync.aligned.m8n8.x4.trans.shared.b16 {%0,%1,%2,%3}, [%4];" \
        : "=r"((r)[0]), "=r"((r)[1]), "=r"((r)[2]), "=r"((r)[3]) : "r"(addr))
#define MMA(c, a, b) \
    asm volatile("mma.sync.aligned.m16n8k16.row.col.f32.bf16.bf16.f32 " \
        "{%0,%1,%2,%3}, {%4,%5,%6,%7}, {%8,%9}, {%0,%1,%2,%3};" \
        : "+f"((c)[0]), "+f"((c)[1]), "+f"((c)[2]), "+f"((c)[3]) \
        : "r"((a)[0]), "r"((a)[1]), "r"((a)[2]), "r"((a)[3]), "r"((b)[0]), "r"((b)[1]))
#define CP_ASYNC16(dst, src) \
    asm volatile("cp.async.cg.shared.global [%0], [%1], 16;" :: "r"(dst), "l"(src) : "memory")
#define CP_COMMIT() asm volatile("cp.async.commit_group;" ::: "memory")
#define CP_WAIT1()  asm volatile("cp.async.wait_group 1;" ::: "memory")

/* ================= K0: qbias[j] = (question[j] . w_q) * log2(e) ================= */
__global__ void qbias_kernel(const float* __restrict__ x, const float* __restrict__ kern) {
    int j = blockIdx.x * 8 + (threadIdx.x >> 5);
    int lane = threadIdx.x & 31;
    const float* q  = x + (size_t)T_DIM * D_DIM + (size_t)j * D_DIM;
    const float* wq = kern + D_DIM;
    float s = q[lane] * wq[lane] + q[lane + 32] * wq[lane + 32]
            + q[lane + 64] * wq[lane + 64] + q[lane + 96] * wq[lane + 96];
    #pragma unroll
    for (int off = 16; off; off >>= 1) s += __shfl_xor_sync(0xffffffffu, s, off);
    if (lane == 0) g_qbias[j] = s * LOG2E;
}

/* ================= K0b: pre-convert K to swizzled bf16 hi/lo tile blobs ================= */
__global__ void kconv_kernel(const float* __restrict__ x) {
    const float* qst = x + (size_t)T_DIM * D_DIM;
    const int gt  = blockIdx.x;           /* tile of 64 keys */
    const int tid = threadIdx.x;
    const int sch = tid & 15, srow0 = tid >> 4;
    unsigned char* dst = g_kswz + (size_t)gt * BUF_STRIDE;
    #pragma unroll
    for (int i = 0; i < 4; ++i) {
        int row = srow0 + 16 * i;
        const float* src = qst + (size_t)(gt * BN + row) * D_DIM + sch * 8;
        float4 v0 = *(const float4*)src, v1 = *(const float4*)(src + 4);
        uint32_t h0, l0, h1, l1, h2, l2, h3, l3;
        split2(v0.x, v0.y, h0, l0); split2(v0.z, v0.w, h1, l1);
        split2(v1.x, v1.y, h2, l2); split2(v1.z, v1.w, h3, l3);
        uint32_t off = row * 256 + ((sch ^ (row & 7)) << 4);
        *(uint4*)(dst + off)              = make_uint4(h0, h1, h2, h3);
        *(uint4*)(dst + OFF_KL_REL + off) = make_uint4(l0, l1, l2, l3);
    }
}

/* ================= K1: HMMA flash, cp.async triple-buffered K ================= */
__global__ void __launch_bounds__(NTH, 1)
flash_kernel(const float* __restrict__ x, const float* __restrict__ kern)
{
    extern __shared__ char smem[];
    const uint32_t sb = smem_u32(smem);

    const int tid  = threadIdx.x;
    const int lane = tid & 31;
    const int w    = tid >> 5;
    const int rowblk = blockIdx.x >> 1;
    const int split  = blockIdx.x & 1;
    const int row0 = rowblk * BM;

    const float* ctx = x;
    const float* wm  = kern + 2 * D_DIM;

    /* ---- prologue A: Q' = ctx*w_m*log2e → bf16 hi/lo staged in bufs 0/1 ---- */
    #pragma unroll
    for (int i = 0; i < 8; ++i) {
        int idx = tid + i * NTH;
        int row = idx >> 4, ch = idx & 15;
        const float* src = ctx + (size_t)(row0 + row) * D_DIM + ch * 8;
        float4 v0 = *(const float4*)src, v1 = *(const float4*)(src + 4);
        float4 w0 = *(const float4*)&wm[ch * 8], w1 = *(const float4*)&wm[ch * 8 + 4];
        w0.x *= LOG2E; w0.y *= LOG2E; w0.z *= LOG2E; w0.w *= LOG2E;
        w1.x *= LOG2E; w1.y *= LOG2E; w1.z *= LOG2E; w1.w *= LOG2E;
        v0.x *= w0.x; v0.y *= w0.y; v0.z *= w0.z; v0.w *= w0.w;
        v1.x *= w1.x; v1.y *= w1.y; v1.z *= w1.z; v1.w *= w1.w;
        uint32_t h0, l0, h1, l1, h2, l2, h3, l3;
        split2(v0.x, v0.y, h0, l0); split2(v0.z, v0.w, h1, l1);
        split2(v1.x, v1.y, h2, l2); split2(v1.z, v1.w, h3, l3);
        uint32_t off = row * 256 + ((ch ^ (row & 7)) << 4);
        *(uint4*)(smem + off)              = make_uint4(h0, h1, h2, h3);
        *(uint4*)(smem + BUF_STRIDE + off) = make_uint4(l0, l1, l2, l3);
    }
    __syncthreads();

    /* ---- prologue B: loop-invariant Q A-fragments into registers ---- */
    const int m0 = w * 16;
    const int a_row = m0 + (lane & 15);
    const int a_cs  = (lane >> 4);
    uint32_t aQh[8][4], aQl[8][4];
    #pragma unroll
    for (int kt = 0; kt < 8; ++kt) {
        int ach = kt * 2 + a_cs;
        uint32_t aoff = a_row * 256 + ((ach ^ (a_row & 7)) << 4);
        LDSM4(aQh[kt], sb + aoff);
        LDSM4(aQl[kt], sb + BUF_STRIDE + aoff);
    }
    __syncthreads();   /* Q reads done — buffers free for K pipeline */

    /* ---- prologue C: cp.async K tile 0 → buf0 (group 0) ---- */
    const unsigned char* ksrc = g_kswz + (size_t)(split * NTILES) * BUF_STRIDE;
    {
        const unsigned char* src = ksrc + tid * 128;
        uint32_t dst = sb + tid * 128;
        #pragma unroll
        for (int j = 0; j < 8; ++j) CP_ASYNC16(dst + j * 16, src + j * 16);
        if (tid < 16)
            CP_ASYNC16(sb + OFF_QB + tid * 16,
                       (const unsigned char*)(g_qbias + split * KEYS_PER_SPLIT) + tid * 16);
        CP_COMMIT();
    }

    float O[16][4];
    float msc0 = 0.f, msc1 = 0.f;
    float l0r = 0.f, l1r = 0.f;
    float pm0 = 0.f, pm1 = 0.f;
    #pragma unroll
    for (int nt = 0; nt < 16; ++nt)
        #pragma unroll
        for (int c = 0; c < 4; ++c) O[nt][c] = 0.f;

    const int b1_key = ((lane >> 4) << 3) + (lane & 7);
    const int b1_cs  = ((lane >> 3) & 1);
    const int b2_key = ((lane >> 3) & 1) * 8 + (lane & 7);
    const int b2_cs  = (lane >> 4);

    for (int t = 0; t < NTILES; ++t) {
        /* issue cp.async for tile t+1 into buf[(t+1)%3] */
        if (t + 1 < NTILES) {
            const unsigned char* src = ksrc + (size_t)(t + 1) * BUF_STRIDE + tid * 128;
            uint32_t dst = sb + (uint32_t)((t + 1) % 3) * BUF_STRIDE + tid * 128;
            #pragma unroll
            for (int j = 0; j < 8; ++j) CP_ASYNC16(dst + j * 16, src + j * 16);
            if (tid < 16)
                CP_ASYNC16(sb + OFF_QB + ((t + 1) % 3) * 256 + tid * 16,
                           (const unsigned char*)(g_qbias + split * KEYS_PER_SPLIT + (t + 1) * BN) + tid * 16);
        }
        CP_COMMIT();
        CP_WAIT1();        /* group t complete (this thread) */
        __syncthreads();   /* all threads' copies visible; buffers rotated safely */

        const uint32_t bufR = sb + (uint32_t)(t % 3) * BUF_STRIDE;

        /* ---- GEMM1: S = Qh*Kh + Ql*Kh + Qh*Kl ---- */
        float S[8][4];
        #pragma unroll
        for (int nt = 0; nt < 8; ++nt) {
            S[nt][0] = 0.f; S[nt][1] = 0.f; S[nt][2] = 0.f; S[nt][3] = 0.f;
        }
        #pragma unroll
        for (int kt = 0; kt < 8; ++kt) {
            uint32_t bh[4][4];
            #pragma unroll
            for (int np = 0; np < 4; ++np) {
                int key = np * 16 + b1_key;
                int ch  = kt * 2 + b1_cs;
                LDSM4(bh[np], bufR + key * 256 + ((ch ^ (key & 7)) << 4));
            }
            #pragma unroll
            for (int np = 0; np < 4; ++np) {
                MMA(S[2 * np],     aQh[kt], &bh[np][0]);
                MMA(S[2 * np + 1], aQh[kt], &bh[np][2]);
            }
            #pragma unroll
            for (int np = 0; np < 4; ++np) {
                MMA(S[2 * np],     aQl[kt], &bh[np][0]);
                MMA(S[2 * np + 1], aQl[kt], &bh[np][2]);
            }
            #pragma unroll
            for (int np = 0; np < 4; ++np) {   /* reuse regs for Kl */
                int key = np * 16 + b1_key;
                int ch  = kt * 2 + b1_cs;
                LDSM4(bh[np], bufR + OFF_KL_REL + key * 256 + ((ch ^ (key & 7)) << 4));
            }
            #pragma unroll
            for (int np = 0; np < 4; ++np) {
                MMA(S[2 * np],     aQh[kt], &bh[np][0]);
                MMA(S[2 * np + 1], aQh[kt], &bh[np][2]);
            }
        }

        /* ---- static-scale base-2 softmax ---- */
        uint32_t P[8][2];
        {
            const float* qbp = (const float*)(smem + OFF_QB + (t % 3) * 256);
            #pragma unroll
            for (int nt = 0; nt < 8; ++nt) {
                float2 tq = *(const float2*)&qbp[nt * 8 + (lane & 3) * 2];
                S[nt][0] += tq.x; S[nt][1] += tq.y;
                S[nt][2] += tq.x; S[nt][3] += tq.y;
            }
            if (t == 0) {
                float mx0 = -INFINITY, mx1 = -INFINITY;
                #pragma unroll
                for (int nt = 0; nt < 8; ++nt) {
                    mx0 = fmaxf(mx0, fmaxf(S[nt][0], S[nt][1]));
                    mx1 = fmaxf(mx1, fmaxf(S[nt][2], S[nt][3]));
                }
                mx0 = fmaxf(mx0, __shfl_xor_sync(0xffffffffu, mx0, 1));
                mx0 = fmaxf(mx0, __shfl_xor_sync(0xffffffffu, mx0, 2));
                mx1 = fmaxf(mx1, __shfl_xor_sync(0xffffffffu, mx1, 1));
                mx1 = fmaxf(mx1, __shfl_xor_sync(0xffffffffu, mx1, 2));
                msc0 = mx0; msc1 = mx1;
            }
            #pragma unroll
            for (int nt = 0; nt < 8; ++nt) {
                float p0 = ex2(S[nt][0] - msc0);
                float p1 = ex2(S[nt][1] - msc0);
                float p2 = ex2(S[nt][2] - msc1);
                float p3 = ex2(S[nt][3] - msc1);
                l0r += p0 + p1;  l1r += p2 + p3;
                pm0 = fmaxf(pm0, fmaxf(p0, p1));
                pm1 = fmaxf(pm1, fmaxf(p2, p3));
                P[nt][0] = pack_bf16x2(p0, p1);
                P[nt][1] = pack_bf16x2(p2, p3);
            }
        }

        /* ---- GEMM2: O += P * Vh ---- */
        #pragma unroll
        for (int kt2 = 0; kt2 < 4; ++kt2) {
            uint32_t aP[4] = { P[2 * kt2][0], P[2 * kt2][1],
                               P[2 * kt2 + 1][0], P[2 * kt2 + 1][1] };
            const int key = kt2 * 16 + b2_key;
            const uint32_t krow = bufR + key * 256;
            #pragma unroll
            for (int dp = 0; dp < 8; ++dp) {
                uint32_t bv[4];
                int ch = dp * 2 + b2_cs;
                LDSM4T(bv, krow + ((ch ^ (key & 7)) << 4));
                MMA(O[2 * dp],     aP, &bv[0]);
                MMA(O[2 * dp + 1], aP, &bv[2]);
            }
        }
    }

    /* ---- epilogue: one-time l / pm reductions, write O and (msc,pm,l) ---- */
    {
        l0r += __shfl_xor_sync(0xffffffffu, l0r, 1);
        l0r += __shfl_xor_sync(0xffffffffu, l0r, 2);
        l1r += __shfl_xor_sync(0xffffffffu, l1r, 1);
        l1r += __shfl_xor_sync(0xffffffffu, l1r, 2);
        pm0 = fmaxf(pm0, __shfl_xor_sync(0xffffffffu, pm0, 1));
        pm0 = fmaxf(pm0, __shfl_xor_sync(0xffffffffu, pm0, 2));
        pm1 = fmaxf(pm1, __shfl_xor_sync(0xffffffffu, pm1, 1));
        pm1 = fmaxf(pm1, __shfl_xor_sync(0xffffffffu, pm1, 2));

        int r1 = row0 + m0 + (lane >> 2);
        int r2 = r1 + 8;
        if ((lane & 3) == 0) {
            g_ml[(size_t)split * T_DIM + r1] = make_float4(msc0, pm0, l0r, 0.f);
            g_ml[(size_t)split * T_DIM + r2] = make_float4(msc1, pm1, l1r, 0.f);
        }
        float* o1 = g_O + ((size_t)split * T_DIM + r1) * D_DIM + (lane & 3) * 2;
        float* o2 = g_O + ((size_t)split * T_DIM + r2) * D_DIM + (lane & 3) * 2;
        #pragma unroll
        for (int nt = 0; nt < 16; ++nt) {
            *(float2*)(o1 + nt * 8) = make_float2(O[nt][0], O[nt][1]);
            *(float2*)(o2 + nt * 8) = make_float2(O[nt][2], O[nt][3]);
        }
    }
}

/* ============ K2: combine splits, write out cols [0,384), emit b ============ */
__global__ void combine_kernel(const float* __restrict__ x, float* __restrict__ out) {
    int row  = (blockIdx.x * blockDim.x + threadIdx.x) >> 5;
    int lane = threadIdx.x & 31;
    float4 ml[NSPLIT];
    float M = -INFINITY;
    #pragma unroll
    for (int s = 0; s < NSPLIT; ++s) {
        ml[s] = g_ml[(size_t)s * T_DIM + row];
        M = fmaxf(M, ml[s].x);
    }
    float L = 0.f, e[NSPLIT], bmax = 0.f;
    #pragma unroll
    for (int s = 0; s < NSPLIT; ++s) {
        e[s] = ex2(ml[s].x - M);
        L += ml[s].z * e[s];
        bmax = fmaxf(bmax, ml[s].y * e[s]);
    }
    float invL = 1.0f / L;
    float4 U = make_float4(0.f, 0.f, 0.f, 0.f);
    #pragma unroll
    for (int s = 0; s < NSPLIT; ++s) {
        float4 o = *(const float4*)&g_O[((size_t)s * T_DIM + row) * D_DIM + lane * 4];
        U.x += o.x * e[s]; U.y += o.y * e[s]; U.z += o.z * e[s]; U.w += o.w * e[s];
    }
    U.x *= invL; U.y *= invL; U.z *= invL; U.w *= invL;
    float4 c = *(const float4*)&x[(size_t)row * D_DIM + lane * 4];
    float* orow = out + (size_t)row * (4 * D_DIM);
    *(float4*)&orow[lane * 4]             = c;
    *(float4*)&orow[D_DIM + lane * 4]     = U;
    *(float4*)&orow[2 * D_DIM + lane * 4] = make_float4(c.x * U.x, c.y * U.y, c.z * U.z, c.w * U.w);
    if (lane == 0) g_b[row] = bmax * invL;   /* b = max_j A */
}

/* ============ K3/K4/K5: h = b @ context; out cols [384,512) = ctx*h ============ */
__global__ void hpart_kernel(const float* __restrict__ x) {
    int d = threadIdx.x;
    int r0 = blockIdx.x * (T_DIM / HPART_BLKS);
    float s = 0.f;
    #pragma unroll
    for (int r = 0; r < T_DIM / HPART_BLKS; ++r)
        s += g_b[r0 + r] * x[(size_t)(r0 + r) * D_DIM + d];
    g_hpart[blockIdx.x * D_DIM + d] = s;
}
__global__ void hreduce_kernel() {
    int d = threadIdx.x;
    float s = 0.f;
    #pragma unroll 16
    for (int b = 0; b < HPART_BLKS; ++b) s += g_hpart[b * D_DIM + d];
    g_h[d] = s;
}
__global__ void hwrite_kernel(const float* __restrict__ x, float* __restrict__ out) {
    int idx = blockIdx.x * blockDim.x + threadIdx.x;
    int row = idx >> 5;
    int dq  = idx & 31;
    float4 c = ((const float4*)x)[(size_t)row * 32 + dq];
    float4 h = ((const float4*)g_h)[dq];
    ((float4*)out)[(size_t)row * 128 + 96 + dq] =
        make_float4(c.x * h.x, c.y * h.y, c.z * h.z, c.w * h.w);
}

/* ============================================================================ */
extern "C" void kernel_launch(void* const* d_in, const int* in_sizes, int n_in,
                              void* d_out, int out_size) {
    const float* x    = (const float*)d_in[0];
    const float* kern = (const float*)d_in[1];
    float* out = (float*)d_out;

    cudaFuncSetAttribute(flash_kernel, cudaFuncAttributeMaxDynamicSharedMemorySize, SMEM_SZ);

    qbias_kernel<<<T_DIM / 8, 256>>>(x, kern);
    kconv_kernel<<<NTILES_ALL, 256>>>(x);
    flash_kernel<<<(T_DIM / BM) * NSPLIT, NTH, SMEM_SZ>>>(x, kern);
    combine_kernel<<<(T_DIM * 32) / 256, 256>>>(x, out);
    hpart_kernel<<<HPART_BLKS, 128>>>(x);
    hreduce_kernel<<<1, 128>>>();
    hwrite_kernel<<<(T_DIM * D_DIM / 4) / 256, 256>>>(x, out);
}

// round 9
// speedup vs baseline: 1.2468x; 1.2398x over previous
#include <cuda_runtime.h>
#include <cuda_bf16.h>
#include <math.h>
#include <stdint.h>

#define T_DIM 8192
#define D_DIM 128
#define BM 128
#define BN 64
#define NTH 256
#define NCTA 148
#define FT_TOTAL 8192            /* 64 rowblocks * 128 keytiles */
#define LOG2E 1.4426950408889634f

/* smem: two 32KB K buffers (KH 16K | KL 16K) + qbias double buffer */
#define BUF_STRIDE 32768
#define OFF_KL_REL 16384
#define OFF_QB 65536
#define SMEM_SZ 66048

#define HPART_BLKS 512

__device__ float  g_qbias[T_DIM];
__device__ float  g_O[4 * T_DIM * D_DIM];     /* 4 slots; unwritten stay 0 */
__device__ float4 g_ml[4 * T_DIM];            /* (m_scale, p_max, l, 0)    */
__device__ float  g_b[T_DIM];
__device__ float  g_hpart[HPART_BLKS * D_DIM];
__device__ float  g_h[D_DIM];

__device__ __forceinline__ uint32_t smem_u32(const void* p) {
    uint32_t a;
    asm("{ .reg .u64 t; cvta.to.shared.u64 t, %1; cvt.u32.u64 %0, t; }" : "=r"(a) : "l"(p));
    return a;
}
__device__ __forceinline__ float ex2(float x) {
    float y;
    asm("ex2.approx.f32 %0, %1;" : "=f"(y) : "f"(x));
    return y;
}
/* pack two floats to bf16x2: lower 16 = first arg */
__device__ __forceinline__ uint32_t pack_bf16x2(float lo, float hi) {
    uint32_t r;
    asm("cvt.rn.bf16x2.f32 %0, %1, %2;" : "=r"(r) : "f"(hi), "f"(lo));
    return r;
}
__device__ __forceinline__ void split2(float a, float b, uint32_t& hi, uint32_t& lo) {
    hi = pack_bf16x2(a, b);
    float fa = __uint_as_float(hi << 16);
    float fb = __uint_as_float(hi & 0xffff0000u);
    lo = pack_bf16x2(a - fa, b - fb);
}

#define LDSM4(r, addr) \
    asm volatile("ldmatrix.sync.aligned.m8n8.x4.shared.b16 {%0,%1,%2,%3}, [%4];" \
        : "=r"((r)[0]), "=r"((r)[1]), "=r"((r)[2]), "=r"((r)[3]) : "r"(addr))
#define LDSM4T(r, addr) \
    asm volatile("ldmatrix.sync.aligned.m8n8.x4.trans.shared.b16 {%0,%1,%2,%3}, [%4];" \
        : "=r"((r)[0]), "=r"((r)[1]), "=r"((r)[2]), "=r"((r)[3]) : "r"(addr))
#define MMA(c, a, b) \
    asm volatile("mma.sync.aligned.m16n8k16.row.col.f32.bf16.bf16.f32 " \
        "{%0,%1,%2,%3}, {%4,%5,%6,%7}, {%8,%9}, {%0,%1,%2,%3};" \
        : "+f"((c)[0]), "+f"((c)[1]), "+f"((c)[2]), "+f"((c)[3]) \
        : "r"((a)[0]), "r"((a)[1]), "r"((a)[2]), "r"((a)[3]), "r"((b)[0]), "r"((b)[1]))

/* ================= K0: qbias[j] = (question[j] . w_q) * log2(e) ================= */
__global__ void qbias_kernel(const float* __restrict__ x, const float* __restrict__ kern) {
    int j = blockIdx.x * 8 + (threadIdx.x >> 5);
    int lane = threadIdx.x & 31;
    const float* q  = x + (size_t)T_DIM * D_DIM + (size_t)j * D_DIM;
    const float* wq = kern + D_DIM;
    float s = q[lane] * wq[lane] + q[lane + 32] * wq[lane + 32]
            + q[lane + 64] * wq[lane + 64] + q[lane + 96] * wq[lane + 96];
    #pragma unroll
    for (int off = 16; off; off >>= 1) s += __shfl_xor_sync(0xffffffffu, s, off);
    if (lane == 0) g_qbias[j] = s * LOG2E;
}

/* ================= K1: HMMA flash, balanced 148-CTA static schedule ================= */
__global__ void __launch_bounds__(NTH, 1)
flash_kernel(const float* __restrict__ x, const float* __restrict__ kern)
{
    extern __shared__ char smem[];
    const uint32_t sb = smem_u32(smem);

    const int tid  = threadIdx.x;
    const int lane = tid & 31;
    const int w    = tid >> 5;
    const int cta  = blockIdx.x;
    const int ft0  = (FT_TOTAL * cta) / NCTA;
    const int ft1  = (FT_TOTAL * (cta + 1)) / NCTA;
    const int slot = cta & 3;

    const float* ctx = x;
    const float* qst = x + (size_t)T_DIM * D_DIM;
    const float* wm  = kern + 2 * D_DIM;

    const int m0 = w * 16;
    const int a_row = m0 + (lane & 15);
    const int a_cs  = (lane >> 4);
    const int b1_key = ((lane >> 4) << 3) + (lane & 7);
    const int b1_cs  = ((lane >> 3) & 1);
    const int b2_key = ((lane >> 3) & 1) * 8 + (lane & 7);
    const int b2_cs  = (lane >> 4);
    const int srow = tid >> 4, sch = tid & 15;

    int ft = ft0;
    while (ft < ft1) {
        const int ra   = ft >> 7;                 /* rowblock of this segment */
        const int tend = min(ft1, (ra + 1) << 7);
        const int kt0  = ft & 127;                /* first global key-tile    */
        const int ntl  = tend - ft;               /* tiles in this segment    */
        const int row0 = ra * BM;

        __syncthreads();   /* prior segment's smem reads complete */

        /* ---- prologue A: Q' = ctx*w_m*log2e → bf16 hi/lo staged in bufs 0/1 ---- */
        #pragma unroll
        for (int i = 0; i < 8; ++i) {
            int idx = tid + i * NTH;
            int row = idx >> 4, ch = idx & 15;
            const float* src = ctx + (size_t)(row0 + row) * D_DIM + ch * 8;
            float4 v0 = *(const float4*)src, v1 = *(const float4*)(src + 4);
            float4 w0 = *(const float4*)&wm[ch * 8], w1 = *(const float4*)&wm[ch * 8 + 4];
            w0.x *= LOG2E; w0.y *= LOG2E; w0.z *= LOG2E; w0.w *= LOG2E;
            w1.x *= LOG2E; w1.y *= LOG2E; w1.z *= LOG2E; w1.w *= LOG2E;
            v0.x *= w0.x; v0.y *= w0.y; v0.z *= w0.z; v0.w *= w0.w;
            v1.x *= w1.x; v1.y *= w1.y; v1.z *= w1.z; v1.w *= w1.w;
            uint32_t h0, l0, h1, l1, h2, l2, h3, l3;
            split2(v0.x, v0.y, h0, l0); split2(v0.z, v0.w, h1, l1);
            split2(v1.x, v1.y, h2, l2); split2(v1.z, v1.w, h3, l3);
            uint32_t off = row * 256 + ((ch ^ (row & 7)) << 4);
            *(uint4*)(smem + off)              = make_uint4(h0, h1, h2, h3);
            *(uint4*)(smem + BUF_STRIDE + off) = make_uint4(l0, l1, l2, l3);
        }
        __syncthreads();

        /* ---- prologue B: loop-invariant Q A-fragments into registers ---- */
        uint32_t aQh[8][4], aQl[8][4];
        #pragma unroll
        for (int kt = 0; kt < 8; ++kt) {
            int ach = kt * 2 + a_cs;
            uint32_t aoff = a_row * 256 + ((ach ^ (a_row & 7)) << 4);
            LDSM4(aQh[kt], sb + aoff);
            LDSM4(aQl[kt], sb + BUF_STRIDE + aoff);
        }
        __syncthreads();   /* Q reads done — buffers free for K */

        /* ---- prologue C: K tile kt0 → buf0 ---- */
        {
            const int kb = kt0 * BN;
            #pragma unroll
            for (int i = 0; i < 4; ++i) {
                int row = srow + 16 * i;
                const float* src = qst + (size_t)(kb + row) * D_DIM + sch * 8;
                float4 v0 = *(const float4*)src, v1 = *(const float4*)(src + 4);
                uint32_t h0, l0, h1, l1, h2, l2, h3, l3;
                split2(v0.x, v0.y, h0, l0); split2(v0.z, v0.w, h1, l1);
                split2(v1.x, v1.y, h2, l2); split2(v1.z, v1.w, h3, l3);
                uint32_t off = row * 256 + ((sch ^ (row & 7)) << 4);
                *(uint4*)(smem + off)              = make_uint4(h0, h1, h2, h3);
                *(uint4*)(smem + OFF_KL_REL + off) = make_uint4(l0, l1, l2, l3);
            }
            if (tid < BN) ((float*)(smem + OFF_QB))[tid] = g_qbias[kb + tid];
        }

        float O[16][4];
        float msc0 = 0.f, msc1 = 0.f;
        float l0r = 0.f, l1r = 0.f;
        float pm0 = 0.f, pm1 = 0.f;
        #pragma unroll
        for (int nt = 0; nt < 16; ++nt)
            #pragma unroll
            for (int c = 0; c < 4; ++c) O[nt][c] = 0.f;

        for (int t = 0; t < ntl; ++t) {
            __syncthreads();   /* buf[t&1] ready; buf[(t+1)&1] free */
            const uint32_t bufR = sb + (uint32_t)(t & 1) * BUF_STRIDE;
            const uint32_t bufW = (uint32_t)((t + 1) & 1) * BUF_STRIDE;
            const bool has_next = (t + 1 < ntl);

            /* stage fp32 loads of K tile t+1 (latency hidden under GEMM1) */
            float4 sA[4], sB[4];
            float sqb = 0.f;
            if (has_next) {
                const int kb = (kt0 + t + 1) * BN;
                #pragma unroll
                for (int i = 0; i < 4; ++i) {
                    const float* src = qst + (size_t)(kb + srow + 16 * i) * D_DIM + sch * 8;
                    sA[i] = *(const float4*)src;
                    sB[i] = *(const float4*)(src + 4);
                }
                if (tid < BN) sqb = g_qbias[kb + tid];
            }

            /* ---- GEMM1: S = bias + Qh*Kh + Ql*Kh + Qh*Kl ---- */
            float S[8][4];
            {
                const float* qbp = (const float*)(smem + OFF_QB + (t & 1) * 256);
                #pragma unroll
                for (int nt = 0; nt < 8; ++nt) {
                    float2 tq = *(const float2*)&qbp[nt * 8 + (lane & 3) * 2];
                    S[nt][0] = tq.x; S[nt][1] = tq.y;
                    S[nt][2] = tq.x; S[nt][3] = tq.y;
                }
            }
            #pragma unroll
            for (int kt = 0; kt < 8; ++kt) {
                uint32_t bh[4][4];
                #pragma unroll
                for (int np = 0; np < 4; ++np) {
                    int key = np * 16 + b1_key;
                    int ch  = kt * 2 + b1_cs;
                    LDSM4(bh[np], bufR + key * 256 + ((ch ^ (key & 7)) << 4));
                }
                #pragma unroll
                for (int np = 0; np < 4; ++np) {
                    MMA(S[2 * np],     aQh[kt], &bh[np][0]);
                    MMA(S[2 * np + 1], aQh[kt], &bh[np][2]);
                }
                #pragma unroll
                for (int np = 0; np < 4; ++np) {
                    MMA(S[2 * np],     aQl[kt], &bh[np][0]);
                    MMA(S[2 * np + 1], aQl[kt], &bh[np][2]);
                }
                #pragma unroll
                for (int np = 0; np < 4; ++np) {   /* reuse regs for Kl */
                    int key = np * 16 + b1_key;
                    int ch  = kt * 2 + b1_cs;
                    LDSM4(bh[np], bufR + OFF_KL_REL + key * 256 + ((ch ^ (key & 7)) << 4));
                }
                #pragma unroll
                for (int np = 0; np < 4; ++np) {
                    MMA(S[2 * np],     aQh[kt], &bh[np][0]);
                    MMA(S[2 * np + 1], aQh[kt], &bh[np][2]);
                }
            }

            /* ---- convert + store staged tile t+1 into the free buffer ---- */
            if (has_next) {
                #pragma unroll
                for (int i = 0; i < 4; ++i) {
                    int row = srow + 16 * i;
                    uint32_t h0, l0, h1, l1, h2, l2, h3, l3;
                    split2(sA[i].x, sA[i].y, h0, l0); split2(sA[i].z, sA[i].w, h1, l1);
                    split2(sB[i].x, sB[i].y, h2, l2); split2(sB[i].z, sB[i].w, h3, l3);
                    uint32_t off = row * 256 + ((sch ^ (row & 7)) << 4);
                    *(uint4*)(smem + bufW + off)              = make_uint4(h0, h1, h2, h3);
                    *(uint4*)(smem + bufW + OFF_KL_REL + off) = make_uint4(l0, l1, l2, l3);
                }
                if (tid < BN) ((float*)(smem + OFF_QB + ((t + 1) & 1) * 256))[tid] = sqb;
            }

            /* ---- static-scale base-2 softmax ---- */
            uint32_t P[8][2];
            {
                if (t == 0) {
                    float mx0 = -INFINITY, mx1 = -INFINITY;
                    #pragma unroll
                    for (int nt = 0; nt < 8; ++nt) {
                        mx0 = fmaxf(mx0, fmaxf(S[nt][0], S[nt][1]));
                        mx1 = fmaxf(mx1, fmaxf(S[nt][2], S[nt][3]));
                    }
                    mx0 = fmaxf(mx0, __shfl_xor_sync(0xffffffffu, mx0, 1));
                    mx0 = fmaxf(mx0, __shfl_xor_sync(0xffffffffu, mx0, 2));
                    mx1 = fmaxf(mx1, __shfl_xor_sync(0xffffffffu, mx1, 1));
                    mx1 = fmaxf(mx1, __shfl_xor_sync(0xffffffffu, mx1, 2));
                    msc0 = mx0; msc1 = mx1;
                }
                #pragma unroll
                for (int nt = 0; nt < 8; ++nt) {
                    float p0 = ex2(S[nt][0] - msc0);
                    float p1 = ex2(S[nt][1] - msc0);
                    float p2 = ex2(S[nt][2] - msc1);
                    float p3 = ex2(S[nt][3] - msc1);
                    l0r += p0 + p1;  l1r += p2 + p3;
                    pm0 = fmaxf(pm0, fmaxf(p0, p1));
                    pm1 = fmaxf(pm1, fmaxf(p2, p3));
                    P[nt][0] = pack_bf16x2(p0, p1);
                    P[nt][1] = pack_bf16x2(p2, p3);
                }
            }

            /* ---- GEMM2: O += P * Vh ---- */
            #pragma unroll
            for (int kt2 = 0; kt2 < 4; ++kt2) {
                uint32_t aP[4] = { P[2 * kt2][0], P[2 * kt2][1],
                                   P[2 * kt2 + 1][0], P[2 * kt2 + 1][1] };
                const int key = kt2 * 16 + b2_key;
                const uint32_t krow = bufR + key * 256;
                #pragma unroll
                for (int dp = 0; dp < 8; ++dp) {
                    uint32_t bv[4];
                    int ch = dp * 2 + b2_cs;
                    LDSM4T(bv, krow + ((ch ^ (key & 7)) << 4));
                    MMA(O[2 * dp],     aP, &bv[0]);
                    MMA(O[2 * dp + 1], aP, &bv[2]);
                }
            }
        }

        /* ---- segment epilogue: reduce l/pm, write slot ---- */
        {
            l0r += __shfl_xor_sync(0xffffffffu, l0r, 1);
            l0r += __shfl_xor_sync(0xffffffffu, l0r, 2);
            l1r += __shfl_xor_sync(0xffffffffu, l1r, 1);
            l1r += __shfl_xor_sync(0xffffffffu, l1r, 2);
            pm0 = fmaxf(pm0, __shfl_xor_sync(0xffffffffu, pm0, 1));
            pm0 = fmaxf(pm0, __shfl_xor_sync(0xffffffffu, pm0, 2));
            pm1 = fmaxf(pm1, __shfl_xor_sync(0xffffffffu, pm1, 1));
            pm1 = fmaxf(pm1, __shfl_xor_sync(0xffffffffu, pm1, 2));

            int r1 = row0 + m0 + (lane >> 2);
            int r2 = r1 + 8;
            if ((lane & 3) == 0) {
                g_ml[(size_t)slot * T_DIM + r1] = make_float4(msc0, pm0, l0r, 0.f);
                g_ml[(size_t)slot * T_DIM + r2] = make_float4(msc1, pm1, l1r, 0.f);
            }
            float* o1 = g_O + ((size_t)slot * T_DIM + r1) * D_DIM + (lane & 3) * 2;
            float* o2 = g_O + ((size_t)slot * T_DIM + r2) * D_DIM + (lane & 3) * 2;
            #pragma unroll
            for (int nt = 0; nt < 16; ++nt) {
                *(float2*)(o1 + nt * 8) = make_float2(O[nt][0], O[nt][1]);
                *(float2*)(o2 + nt * 8) = make_float2(O[nt][2], O[nt][3]);
            }
        }
        ft = tend;
    }
}

/* ============ K2: combine up to 4 slots, write out cols [0,384), emit b ============ */
__global__ void combine_kernel(const float* __restrict__ x, float* __restrict__ out) {
    int row  = (blockIdx.x * blockDim.x + threadIdx.x) >> 5;
    int lane = threadIdx.x & 31;
    float4 ml[4];
    float M = -INFINITY;
    #pragma unroll
    for (int s = 0; s < 4; ++s) {
        ml[s] = g_ml[(size_t)s * T_DIM + row];
        if (ml[s].z != 0.f) M = fmaxf(M, ml[s].x);
    }
    float L = 0.f, bmax = 0.f;
    float4 U = make_float4(0.f, 0.f, 0.f, 0.f);
    #pragma unroll
    for (int s = 0; s < 4; ++s) {
        if (ml[s].z != 0.f) {          /* warp-uniform branch */
            float e = ex2(ml[s].x - M);
            L += ml[s].z * e;
            bmax = fmaxf(bmax, ml[s].y * e);
            float4 o = *(const float4*)&g_O[((size_t)s * T_DIM + row) * D_DIM + lane * 4];
            U.x += o.x * e; U.y += o.y * e; U.z += o.z * e; U.w += o.w * e;
        }
    }
    float invL = 1.0f / L;
    U.x *= invL; U.y *= invL; U.z *= invL; U.w *= invL;
    float4 c = *(const float4*)&x[(size_t)row * D_DIM + lane * 4];
    float* orow = out + (size_t)row * (4 * D_DIM);
    *(float4*)&orow[lane * 4]             = c;
    *(float4*)&orow[D_DIM + lane * 4]     = U;
    *(float4*)&orow[2 * D_DIM + lane * 4] = make_float4(c.x * U.x, c.y * U.y, c.z * U.z, c.w * U.w);
    if (lane == 0) g_b[row] = bmax * invL;   /* b = max_j A */
}

/* ============ K3/K4/K5: h = b @ context; out cols [384,512) = ctx*h ============ */
__global__ void hpart_kernel(const float* __restrict__ x) {
    int d = threadIdx.x;
    int r0 = blockIdx.x * (T_DIM / HPART_BLKS);
    float s = 0.f;
    #pragma unroll
    for (int r = 0; r < T_DIM / HPART_BLKS; ++r)
        s += g_b[r0 + r] * x[(size_t)(r0 + r) * D_DIM + d];
    g_hpart[blockIdx.x * D_DIM + d] = s;
}
__global__ void hreduce_kernel() {
    int d = threadIdx.x;
    float s = 0.f;
    #pragma unroll 16
    for (int b = 0; b < HPART_BLKS; ++b) s += g_hpart[b * D_DIM + d];
    g_h[d] = s;
}
__global__ void hwrite_kernel(const float* __restrict__ x, float* __restrict__ out) {
    int idx = blockIdx.x * blockDim.x + threadIdx.x;
    int row = idx >> 5;
    int dq  = idx & 31;
    float4 c = ((const float4*)x)[(size_t)row * 32 + dq];
    float4 h = ((const float4*)g_h)[dq];
    ((float4*)out)[(size_t)row * 128 + 96 + dq] =
        make_float4(c.x * h.x, c.y * h.y, c.z * h.z, c.w * h.w);
}

/* ============================================================================ */
extern "C" void kernel_launch(void* const* d_in, const int* in_sizes, int n_in,
                              void* d_out, int out_size) {
    const float* x    = (const float*)d_in[0];
    const float* kern = (const float*)d_in[1];
    float* out = (float*)d_out;

    cudaFuncSetAttribute(flash_kernel, cudaFuncAttributeMaxDynamicSharedMemorySize, SMEM_SZ);

    qbias_kernel<<<T_DIM / 8, 256>>>(x, kern);
    flash_kernel<<<NCTA, NTH, SMEM_SZ>>>(x, kern);
    combine_kernel<<<(T_DIM * 32) / 256, 256>>>(x, out);
    hpart_kernel<<<HPART_BLKS, 128>>>(x);
    hreduce_kernel<<<1, 128>>>();
    hwrite_kernel<<<(T_DIM * D_DIM / 4) / 256, 256>>>(x, out);
}